// round 5
// baseline (speedup 1.0000x reference)
#include <cuda_runtime.h>
#include <cuda_bf16.h>
#include <cstdint>

// ---------------- problem constants ----------------
#define NP 100000
#define NL 80000
#define NG 50000
#define EDG 400000
#define DIN 512
#define DOUT 128
#define TOTROWS 690000
#define XROWS 230000

// relation tables (device constant, static init — no runtime copies)
__constant__ int c_prefix[10] = {0,782,1564,2346,2971,3596,4221,4612,5003,5394};
__constant__ int c_M[9]    = {100000,100000,100000,80000,80000,80000,50000,50000,50000};
__constant__ int c_xoff[9] = {0,0,0,100000,100000,100000,180000,180000,180000};
__constant__ int c_soff[9] = {0,100000,200000,300000,380000,460000,540000,590000,640000};
__constant__ int c_doff[9] = {0,100000,180000,230000,310000,410000,460000,510000,610000};
__constant__ int c_same[9] = {1,0,0,1,0,0,1,0,0};
__constant__ int c_orow[9] = {0,100000,180000,100000,0,180000,180000,0,100000};

struct EdgePtrs { const int* ei[9]; };

// ---------------- device scratch ----------------
__device__ float          g_H[(size_t)TOTROWS * DOUT];
__device__ __nv_bfloat16  g_Xh[(size_t)XROWS * DIN];
__device__ __nv_bfloat16  g_Xl[(size_t)XROWS * DIN];
__device__ __nv_bfloat16  g_Wh[9 * DOUT * DIN];   // [r][n][k]
__device__ __nv_bfloat16  g_Wl[9 * DOUT * DIN];
__device__ float    g_ssrc[TOTROWS];
__device__ float    g_sdst[TOTROWS];
__device__ float    g_den[TOTROWS];
__device__ float    g_e[9 * EDG];
__device__ float    g_wv[9 * 2 * DIN];

// ---------------- helpers ----------------
__device__ __forceinline__ float dot4(float4 a, float4 b) {
    return a.x*b.x + a.y*b.y + a.z*b.z + a.w*b.w;
}
__device__ __forceinline__ uint32_t smem_u32(const void* p) {
    uint32_t a;
    asm("{ .reg .u64 t; cvta.to.shared.u64 t, %1; cvt.u32.u64 %0, t; }" : "=r"(a) : "l"(p));
    return a;
}
__device__ __forceinline__ void cp_async16(uint32_t sdst, const void* gsrc) {
    asm volatile("cp.async.cg.shared.global [%0], [%1], 16;" :: "r"(sdst), "l"(gsrc) : "memory");
}
__device__ __forceinline__ void ldm_x4(uint32_t* r, uint32_t addr) {
    asm volatile("ldmatrix.sync.aligned.m8n8.x4.shared.b16 {%0,%1,%2,%3}, [%4];"
                 : "=r"(r[0]), "=r"(r[1]), "=r"(r[2]), "=r"(r[3]) : "r"(addr));
}
__device__ __forceinline__ void mma16816(float* d, const uint32_t* a, const uint32_t* b) {
    asm volatile("mma.sync.aligned.m16n8k16.row.col.f32.bf16.bf16.f32 "
                 "{%0,%1,%2,%3},{%4,%5,%6,%7},{%8,%9},{%0,%1,%2,%3};"
                 : "+f"(d[0]), "+f"(d[1]), "+f"(d[2]), "+f"(d[3])
                 : "r"(a[0]), "r"(a[1]), "r"(a[2]), "r"(a[3]), "r"(b[0]), "r"(b[1]));
}

// ---------------- K0: init ----------------
__global__ void k_zero_out(float4* out, int n4) {
    int i = blockIdx.x * blockDim.x + threadIdx.x;
    if (i < n4) out[i] = make_float4(0.f, 0.f, 0.f, 0.f);
}
__global__ void k_init_md() {
    int i = blockIdx.x * blockDim.x + threadIdx.x;
    if (i < TOTROWS) { g_den[i] = 0.f; g_ssrc[i] = 0.f; g_sdst[i] = 0.f; }
}

// ---------------- K1: convert X -> bf16 hi/lo ----------------
__global__ void k_cvt_x(const float4* __restrict__ x, int n4, long long off4) {
    int i = blockIdx.x * blockDim.x + threadIdx.x;
    if (i >= n4) return;
    float4 v = x[i];
    __nv_bfloat16 h0 = __float2bfloat16(v.x);
    __nv_bfloat16 h1 = __float2bfloat16(v.y);
    __nv_bfloat16 h2 = __float2bfloat16(v.z);
    __nv_bfloat16 h3 = __float2bfloat16(v.w);
    __nv_bfloat16 l0 = __float2bfloat16(v.x - __bfloat162float(h0));
    __nv_bfloat16 l1 = __float2bfloat16(v.y - __bfloat162float(h1));
    __nv_bfloat16 l2 = __float2bfloat16(v.z - __bfloat162float(h2));
    __nv_bfloat16 l3 = __float2bfloat16(v.w - __bfloat162float(h3));
    size_t base = (size_t)(off4 + i) * 4;
    __nv_bfloat162* ph = (__nv_bfloat162*)(g_Xh + base);
    __nv_bfloat162* pl = (__nv_bfloat162*)(g_Xl + base);
    ph[0] = __nv_bfloat162(h0, h1); ph[1] = __nv_bfloat162(h2, h3);
    pl[0] = __nv_bfloat162(l0, l1); pl[1] = __nv_bfloat162(l2, l3);
}

// ---------------- K1b: W -> transposed bf16 hi/lo ----------------
__global__ void k_cvt_w(const float* __restrict__ W) {
    int idx = blockIdx.x * blockDim.x + threadIdx.x;
    if (idx >= 9 * DIN * DOUT) return;
    int r = idx >> 16;
    int k = (idx >> 7) & 511;
    int n = idx & 127;
    float w = W[idx];
    __nv_bfloat16 h = __float2bfloat16(w);
    __nv_bfloat16 l = __float2bfloat16(w - __bfloat162float(h));
    int o = (r << 16) + n * DIN + k;
    g_Wh[o] = h; g_Wl[o] = l;
}

// ---------------- K2: wv[r][dst] = W[r] @ a_d ----------------
__global__ void k_wv(const float* __restrict__ W, const float* __restrict__ ad_) {
    int idx = blockIdx.x * blockDim.x + threadIdx.x;
    if (idx >= 9 * DIN) return;
    int k = idx & (DIN - 1);
    int r = idx >> 9;
    const float* a = ad_ + r * DOUT;
    const float* w = W + (size_t)r * DIN * DOUT + (size_t)k * DOUT;
    float s = 0.f;
    #pragma unroll 8
    for (int j = 0; j < DOUT; j++) s = fmaf(w[j], a[j], s);
    g_wv[r * 1024 + DIN + k] = s;
}

// ---------------- K3: cross-type dst logits (2 warp dots per node) ----------------
__device__ __forceinline__ float warp_dot512(float4 x0, float4 x1, float4 x2, float4 x3,
                                             const float* vecbase, int lane) {
    const float4* vv = (const float4*)vecbase;
    float s = dot4(x0, vv[lane]) + dot4(x1, vv[lane + 32])
            + dot4(x2, vv[lane + 64]) + dot4(x3, vv[lane + 96]);
    #pragma unroll
    for (int o = 16; o; o >>= 1) s += __shfl_xor_sync(0xffffffffu, s, o);
    return s;
}
__global__ void k_node_dots2(const float* __restrict__ x, int n,
                             int ra, int qa, int rb, int qb) {
    int gw   = (blockIdx.x * blockDim.x + threadIdx.x) >> 5;
    int lane = threadIdx.x & 31;
    if (gw >= n) return;
    const float4* xr = (const float4*)(x + (size_t)gw * DIN);
    float4 x0 = xr[lane], x1 = xr[lane + 32], x2 = xr[lane + 64], x3 = xr[lane + 96];
    float s;
    s = warp_dot512(x0, x1, x2, x3, g_wv + ra * 1024 + DIN, lane); if (!lane) g_sdst[qa + gw] = s;
    s = warp_dot512(x0, x1, x2, x3, g_wv + rb * 1024 + DIN, lane); if (!lane) g_sdst[qb + gw] = s;
}

// ---------------- K4: split-bf16 mma.sync GEMM, all 9 relations, fused <h,a> epilogue ----
#define GST   40960
#define GROWB 80
#define GE_SMEM (2 * GST)

__global__ __launch_bounds__(256, 2)
void k_mma_gemm(const float* __restrict__ att_src, const float* __restrict__ att_dst) {
    extern __shared__ __align__(128) char smem[];
    uint32_t sb = smem_u32(smem);
    int tid  = threadIdx.x;
    int lane = tid & 31;
    int warp = tid >> 5;
    int wm = warp & 1;
    int wn = warp >> 1;

    // block -> (relation, tile)
    int bid = blockIdx.x;
    int rel = 0;
    #pragma unroll
    for (int r = 1; r < 9; r++) if (bid >= c_prefix[r]) rel = r;
    int tile0 = (bid - c_prefix[rel]) * 128;
    int M     = c_M[rel];
    int hoff  = c_soff[rel];
    int doff  = c_doff[rel];
    int same  = c_same[rel];

    const __nv_bfloat16* baseA[2] = { g_Xh + (size_t)c_xoff[rel] * DIN,
                                      g_Xl + (size_t)c_xoff[rel] * DIN };
    const __nv_bfloat16* baseB[2] = { g_Wh + ((size_t)rel << 16), g_Wl + ((size_t)rel << 16) };

    float acc[4][4][4];
    #pragma unroll
    for (int i = 0; i < 4; i++)
        #pragma unroll
        for (int j = 0; j < 4; j++)
            #pragma unroll
            for (int q = 0; q < 4; q++) acc[i][j][q] = 0.f;

    auto load_chunk = [&](int c) {
        uint32_t stb = sb + (c & 1) * GST;
        int kbase = c * 32;
        #pragma unroll
        for (int t = 0; t < 8; t++) {
            int id  = tid + t * 256;
            int buf = id >> 9;
            int rem = id & 511;
            int row = rem >> 2;
            int c16 = rem & 3;
            const __nv_bfloat16* g;
            if (buf < 2) {
                int grow = tile0 + row; if (grow >= M) grow = M - 1;
                g = baseA[buf] + (size_t)grow * DIN;
            } else {
                g = baseB[buf - 2] + (size_t)row * DIN;
            }
            g += kbase + c16 * 8;
            cp_async16(stb + buf * 10240 + row * GROWB + c16 * 16, g);
        }
        asm volatile("cp.async.commit_group;" ::: "memory");
    };

    uint32_t a_off = (uint32_t)(wm * 64 + (lane & 15)) * GROWB + (lane & 16);
    uint32_t b_off = (uint32_t)(wn * 32 + (lane & 7) + ((lane & 16) ? 8 : 0)) * GROWB
                   + ((lane & 8) << 1);

    load_chunk(0);

    for (int c = 0; c < 16; c++) {
        if (c < 15) {
            load_chunk(c + 1);
            asm volatile("cp.async.wait_group 1;" ::: "memory");
        } else {
            asm volatile("cp.async.wait_group 0;" ::: "memory");
        }
        __syncthreads();

        uint32_t stb = sb + (c & 1) * GST;
        uint32_t ah_s = stb;
        uint32_t al_s = stb + 10240;
        uint32_t bh_s = stb + 20480;
        uint32_t bl_s = stb + 30720;

        #pragma unroll
        for (int ks = 0; ks < 2; ks++) {
            uint32_t kb = ks * 32;
            uint32_t AH[4][4], AL[4][4], B[2][4];
            #pragma unroll
            for (int mf = 0; mf < 4; mf++) {
                ldm_x4(AH[mf], ah_s + a_off + mf * (16 * GROWB) + kb);
                ldm_x4(AL[mf], al_s + a_off + mf * (16 * GROWB) + kb);
            }
            #pragma unroll
            for (int g = 0; g < 2; g++)
                ldm_x4(B[g], bh_s + b_off + g * (16 * GROWB) + kb);
            #pragma unroll
            for (int mf = 0; mf < 4; mf++)
                #pragma unroll
                for (int nf = 0; nf < 4; nf++) {
                    const uint32_t* bp = &B[nf >> 1][(nf & 1) * 2];
                    mma16816(acc[mf][nf], AH[mf], bp);
                    mma16816(acc[mf][nf], AL[mf], bp);
                }
            #pragma unroll
            for (int g = 0; g < 2; g++)
                ldm_x4(B[g], bl_s + b_off + g * (16 * GROWB) + kb);
            #pragma unroll
            for (int mf = 0; mf < 4; mf++)
                #pragma unroll
                for (int nf = 0; nf < 4; nf++)
                    mma16816(acc[mf][nf], AH[mf], &B[nf >> 1][(nf & 1) * 2]);
        }
        __syncthreads();
    }

    // ---- epilogue: store H + fused <h, a_src> (and <h, a_dst> for same-type) ----
    float* Cb = g_H + (size_t)hoff * DOUT;
    int r_base = tile0 + wm * 64 + (lane >> 2);
    int c_base = wn * 32 + (lane & 3) * 2;

    float2 asv[4], adv[4];
    const float* ap = att_src + rel * DOUT + c_base;
    const float* dp = att_dst + rel * DOUT + c_base;
    #pragma unroll
    for (int nf = 0; nf < 4; nf++) {
        asv[nf] = *(const float2*)(ap + nf * 8);
        adv[nf] = same ? *(const float2*)(dp + nf * 8) : make_float2(0.f, 0.f);
    }

    #pragma unroll
    for (int mf = 0; mf < 4; mf++) {
        #pragma unroll
        for (int h = 0; h < 2; h++) {
            int r = r_base + mf * 16 + 8 * h;
            // store H
            #pragma unroll
            for (int nf = 0; nf < 4; nf++) {
                if (r < M)
                    *(float2*)(Cb + (size_t)r * DOUT + c_base + nf * 8)
                        = make_float2(acc[mf][nf][2*h], acc[mf][nf][2*h + 1]);
            }
            // fused dots
            float ps = 0.f, pd = 0.f;
            #pragma unroll
            for (int nf = 0; nf < 4; nf++) {
                ps += acc[mf][nf][2*h] * asv[nf].x + acc[mf][nf][2*h + 1] * asv[nf].y;
                pd += acc[mf][nf][2*h] * adv[nf].x + acc[mf][nf][2*h + 1] * adv[nf].y;
            }
            ps += __shfl_xor_sync(0xffffffffu, ps, 1);
            ps += __shfl_xor_sync(0xffffffffu, ps, 2);
            pd += __shfl_xor_sync(0xffffffffu, pd, 1);
            pd += __shfl_xor_sync(0xffffffffu, pd, 2);
            if ((lane & 3) == 0 && r < M) {
                atomicAdd(&g_ssrc[hoff + r], ps);
                if (same) atomicAdd(&g_sdst[doff + r], pd);
            }
        }
    }
}

// ---------------- K5: fused edge pass (logit -> exp -> denom), all 9 relations ----
#define EBPR 1563   // blocks per relation (1563*256 >= 400000)
__global__ void k_edge_pass(EdgePtrs ep) {
    int rel = blockIdx.x / EBPR;
    int e = (blockIdx.x - rel * EBPR) * 256 + threadIdx.x;
    if (e >= EDG) return;
    const int* ei = ep.ei[rel];
    int s = ei[e], d = ei[EDG + e];
    float a = g_ssrc[c_soff[rel] + s] + g_sdst[c_doff[rel] + d];
    a = (a > 0.f) ? a : 0.2f * a;
    float v = __expf(a);               // |a| <= ~10: no overflow, max-sub not needed
    g_e[rel * EDG + e] = v;
    atomicAdd(&g_den[c_doff[rel] + d], v);
}

// ---------------- K6: weighted scatter, all 9 relations ----------------
#define SBPR 50000  // blocks per relation: 8 edges/block * 50000 = 400000
__global__ void k_edge_scatter(EdgePtrs ep, float* __restrict__ out) {
    int rel = blockIdx.x / SBPR;
    int t = (blockIdx.x - rel * SBPR) * 256 + threadIdx.x;
    int w = t >> 5, lane = t & 31;
    const int* ei = ep.ei[rel];
    int s = ei[w], d = ei[EDG + w];
    float wt = g_e[rel * EDG + w] / g_den[c_doff[rel] + d];
    const float4* h = (const float4*)(g_H + ((size_t)c_soff[rel] + s) * DOUT);
    float4 v = h[lane];
    float* p = out + ((size_t)c_orow[rel] + d) * DOUT + lane * 4;
    asm volatile("red.global.add.v4.f32 [%0], {%1,%2,%3,%4};"
                 :: "l"(p), "f"(v.x * wt), "f"(v.y * wt), "f"(v.z * wt), "f"(v.w * wt)
                 : "memory");
}

// ---------------- K7: mean + bias + relu (all types, one launch) ----------------
__global__ void k_finalize(float* out, const float* __restrict__ bias) {
    int idx = blockIdx.x * blockDim.x + threadIdx.x;
    if (idx >= XROWS * DOUT) return;
    int row = idx >> 7;
    int j = idx & (DOUT - 1);
    int ra, rb, rc;
    if (row < NP)            { ra = 0; rb = 4; rc = 7; }
    else if (row < NP + NL)  { ra = 1; rb = 3; rc = 8; }
    else                     { ra = 2; rb = 5; rc = 6; }
    float b = bias[ra * DOUT + j] + bias[rb * DOUT + j] + bias[rc * DOUT + j];
    float v = (out[idx] + b) * (1.0f / 3.0f);
    out[idx] = (v > 0.f) ? v : 0.f;
}

// ---------------- launch ----------------
extern "C" void kernel_launch(void* const* d_in, const int* in_sizes, int n_in,
                              void* d_out, int out_size) {
    const float* X[3] = {(const float*)d_in[0], (const float*)d_in[1], (const float*)d_in[2]};
    EdgePtrs ep;
    for (int r = 0; r < 9; r++) ep.ei[r] = (const int*)d_in[3 + r];
    const float* W    = (const float*)d_in[12];
    const float* as_  = (const float*)d_in[13];
    const float* ad_  = (const float*)d_in[14];
    const float* bias = (const float*)d_in[15];
    float* out = (float*)d_out;

    cudaFuncSetAttribute(k_mma_gemm, cudaFuncAttributeMaxDynamicSharedMemorySize, GE_SMEM);

    // init
    int n4 = out_size / 4;
    k_zero_out<<<(n4 + 255) / 256, 256>>>((float4*)out, n4);
    k_init_md<<<(TOTROWS + 255) / 256, 256>>>();

    // conversions
    k_cvt_x<<<(NP * 128 + 255) / 256, 256>>>((const float4*)X[0], NP * 128, 0LL);
    k_cvt_x<<<(NL * 128 + 255) / 256, 256>>>((const float4*)X[1], NL * 128, (long long)NP * 128);
    k_cvt_x<<<(NG * 128 + 255) / 256, 256>>>((const float4*)X[2], NG * 128, (long long)(NP + NL) * 128);
    k_cvt_w<<<(9 * DIN * DOUT + 255) / 256, 256>>>(W);

    // dst attention matvec precompute + cross-type dst logits
    k_wv<<<(9 * DIN + 255) / 256, 256>>>(W, ad_);
    k_node_dots2<<<(NP * 32 + 255) / 256, 256>>>(X[0], NP, 4, 310000, 7, 510000);
    k_node_dots2<<<(NL * 32 + 255) / 256, 256>>>(X[1], NL, 1, 100000, 8, 610000);
    k_node_dots2<<<(NG * 32 + 255) / 256, 256>>>(X[2], NG, 2, 180000, 5, 410000);

    // all 9 projections + fused src/same-dst logits, single launch
    k_mma_gemm<<<5394, 256, GE_SMEM>>>(as_, ad_);

    // fused edge softmax (no max pass) + scatter
    k_edge_pass<<<9 * EBPR, 256>>>(ep);
    k_edge_scatter<<<9 * SBPR, 256>>>(ep, out);

    // mean + bias + relu
    k_finalize<<<(XROWS * DOUT + 255) / 256, 256>>>(out, bias);
}